// round 13
// baseline (speedup 1.0000x reference)
#include <cuda_runtime.h>
#include <cstdint>

#define C_       256
#define NBOX_    1024
#define BPC_     2            // boxes per CTA (sequential)
#define THREADS_ 128          // one f32x2 channel-pair per thread

typedef unsigned long long u64;

__device__ __forceinline__ u64 fma2(u64 a, u64 b, u64 c) {
    u64 d; asm("fma.rn.f32x2 %0,%1,%2,%3;" : "=l"(d) : "l"(a), "l"(b), "l"(c)); return d;
}
__device__ __forceinline__ u64 mul2(u64 a, u64 b) {
    u64 d; asm("mul.rn.f32x2 %0,%1,%2;" : "=l"(d) : "l"(a), "l"(b)); return d;
}
__device__ __forceinline__ u64 bcast2(float w) {
    return (u64)__float_as_uint(w) * 0x100000001ULL;
}
__device__ __forceinline__ void stcs64(void* p, u64 v) {
    asm volatile("st.global.cs.b64 [%0],%1;" :: "l"(p), "l"(v) : "memory");
}

__global__ __launch_bounds__(THREADS_) void roialign_kernel(
    const float* __restrict__ feat0,
    const float* __restrict__ feat1,
    const float* __restrict__ rois,
    float* __restrict__ out)
{
    __shared__ int        s_xo0[7], s_xo1[7];   // x corner byte offsets
    __shared__ ulonglong2 s_axbx[7];            // packed x-weights {ax2, bx2} (vx folded)
    __shared__ int        s_yaddr[14];          // distinct-row byte offsets (ylist -> addr)
    __shared__ int        s_ycode[7];           // iy1*2 | (iy0==iy1)
    __shared__ u64        s_wyA[7], s_wyB[7];   // packed y-weights (vy folded)
    __shared__ int        s_dy;

    int t = threadIdx.x;

    for (int it = 0; it < BPC_; it++) {
        int n = blockIdx.x * BPC_ + it;
        if (it) __syncthreads();          // previous box done with smem

        const float* roi = rois + (size_t)n * 5;
        float y1 = roi[0], x1 = roi[1], y2 = roi[2], x2 = roi[3];
        bool L = ((y2 - y1) > 48.0f) || ((x2 - x1) > 48.0f);
        int H = L ? 128 : 256;
        float Hm1 = (float)(H - 1);
        int b = n >> 9;
        const float inv = 1.0f / 1024.0f;

        // ---- x setup: 7 threads, one per pool column ----
        if (t < 7) {
            float x1n = x1 * inv, x2n = x2 * inv;
            float xs = (x1n + (float)t * (1.0f / 6.0f) * (x2n - x1n)) * Hm1;
            float vx = (xs >= 0.0f && xs <= Hm1) ? 1.0f : 0.0f;
            float xf = floorf(xs);
            float wx = xs - xf;
            int x0 = (int)fminf(fmaxf(xf, 0.0f), Hm1);
            int xp = min(x0 + 1, H - 1);
            s_xo0[t] = x0 * (C_ * 4);
            s_xo1[t] = xp * (C_ * 4);
            ulonglong2 ab;
            ab.x = bcast2((1.0f - wx) * vx);
            ab.y = bcast2(wx * vx);
            s_axbx[t] = ab;
        }

        // ---- y setup: single thread builds distinct-row list ----
        if (t == 0) {
            float y1n = y1 * inv, y2n = y2 * inv;
            int dy = 0;
            for (int r = 0; r < 7; r++) {
                float ys = (y1n + (float)r * (1.0f / 6.0f) * (y2n - y1n)) * Hm1;
                float vy = (ys >= 0.0f && ys <= Hm1) ? 1.0f : 0.0f;
                float yf = floorf(ys);
                float wy = ys - yf;
                int y0 = (int)fminf(fmaxf(yf, 0.0f), Hm1);
                int yp = min(y0 + 1, H - 1);

                int i0;
                if (dy > 0 && y0 == s_yaddr[dy - 1])      i0 = dy - 1;
                else if (dy > 1 && y0 == s_yaddr[dy - 2]) i0 = dy - 2;
                else { s_yaddr[dy] = y0; i0 = dy; dy++; }

                int i1;
                if (yp == s_yaddr[dy - 1]) i1 = dy - 1;
                else { s_yaddr[dy] = yp; i1 = dy; dy++; }

                s_ycode[r] = i1 * 2 + ((i0 == i1) ? 1 : 0);
                s_wyA[r] = bcast2((1.0f - wy) * vy);
                s_wyB[r] = bcast2(wy * vy);
            }
            s_dy = dy;
            for (int j = 0; j < dy; j++)
                s_yaddr[j] = ((b * H + s_yaddr[j]) * H) * (C_ * 4);
        }
        __syncthreads();

        // ---- march distinct feature rows ----
        const char* fb = (const char*)(L ? feat1 : feat0);
        int dy = s_dy;

        int xo0[7], xo1[7], ycode[7];
        #pragma unroll
        for (int c = 0; c < 7; c++) {
            xo0[c] = s_xo0[c] + t * 8;
            xo1[c] = s_xo1[c] + t * 8;
            ycode[c] = s_ycode[c];
        }
        char* ob = (char*)out + (size_t)n * 49 * 1024 + t * 8;

        u64 XA[7], XB[7];
        #pragma unroll
        for (int c = 0; c < 7; c++) { XA[c] = 0; XB[c] = 0; }

        auto body = [&](u64 (&cur)[7], u64 (&prv)[7], int j) {
            const char* rb = fb + s_yaddr[j];
            u64 p0[7], p1[7];
            #pragma unroll
            for (int c = 0; c < 7; c++) {
                p0[c] = __ldg((const u64*)(rb + xo0[c]));
                p1[c] = __ldg((const u64*)(rb + xo1[c]));
            }
            #pragma unroll
            for (int c = 0; c < 7; c++) {
                ulonglong2 ab = s_axbx[c];
                cur[c] = fma2(p1[c], ab.y, mul2(p0[c], ab.x));
            }
            // emit pool rows completed by this distinct row
            #pragma unroll
            for (int r = 0; r < 7; r++) {
                if ((ycode[r] >> 1) == j) {
                    bool same = ycode[r] & 1;
                    u64 wA = s_wyA[r];
                    u64 wB = s_wyB[r];
                    #pragma unroll
                    for (int c = 0; c < 7; c++) {
                        u64 xs0 = same ? cur[c] : prv[c];
                        u64 o = fma2(cur[c], wB, mul2(xs0, wA));
                        stcs64(ob + (r * 7 + c) * 1024, o);
                    }
                }
            }
        };

        for (int j = 0; j < dy; ) {
            body(XA, XB, j); j++;
            if (j < dy) { body(XB, XA, j); j++; }
        }
    }
}

extern "C" void kernel_launch(void* const* d_in, const int* in_sizes, int n_in,
                              void* d_out, int out_size)
{
    const float* feat0 = (const float*)d_in[0];
    const float* feat1 = (const float*)d_in[1];
    const float* rois  = (const float*)d_in[2];
    float* out = (float*)d_out;

    roialign_kernel<<<NBOX_ / BPC_, THREADS_>>>(feat0, feat1, rois, out);
}